// round 1
// baseline (speedup 1.0000x reference)
#include <cuda_runtime.h>
#include <cuda_bf16.h>
#include <math.h>

// Problem constants (from reference): N=50000, E=1.6M, F=128, HID=128, LAT=64
#define NMAX 50048

// ---------------- scratch (device globals; no allocation allowed) -----------
__device__ float g_t[(size_t)NMAX * 128];    // x@W1, etc.
__device__ float g_acc[(size_t)NMAX * 128];  // aggregation accumulator (reused)
__device__ float g_h[(size_t)NMAX * 128];    // hidden after relu
__device__ float g_az[(size_t)NMAX * 64];    // aggregated z
__device__ float g_dinv[NMAX];               // degree -> deg^-0.5

// ---------------- degree / norm ---------------------------------------------
__global__ void deg_init(int n) {
    int i = blockIdx.x * blockDim.x + threadIdx.x;
    if (i < n) g_dinv[i] = 1.0f;  // self loop
}
__global__ void deg_count(const int* __restrict__ dst, int e) {
    int i = blockIdx.x * blockDim.x + threadIdx.x;
    if (i < e) atomicAdd(&g_dinv[dst[i]], 1.0f);
}
__global__ void deg_finish(int n) {
    int i = blockIdx.x * blockDim.x + threadIdx.x;
    if (i < n) g_dinv[i] = rsqrtf(g_dinv[i]);  // deg >= 1 always
}

// ---------------- generic fp32 GEMM: C = act(A[N,K] @ B[K,M] + bias) --------
// 64x64 tile, 256 threads, 4x4 per thread, BK=16. K,M multiples of 16/64.
__global__ __launch_bounds__(256) void sgemm_bias(
    const float* __restrict__ A, const float* __restrict__ B,
    const float* __restrict__ bias, float* __restrict__ C,
    int N, int K, int M, int doRelu)
{
    __shared__ float As[16][64];
    __shared__ float Bs[16][64];
    int tid = threadIdx.x;
    int tx = tid & 15, ty = tid >> 4;
    int rowBase = blockIdx.y * 64;
    int colBase = blockIdx.x * 64;

    float acc[4][4];
#pragma unroll
    for (int i = 0; i < 4; i++)
#pragma unroll
        for (int j = 0; j < 4; j++) acc[i][j] = 0.f;

    int aRow  = rowBase + (tid >> 2);   // 4 threads per row, 64 rows
    int aColT = (tid & 3) * 4;
    int bRowT = tid >> 4;               // 16 threads per row, 16 rows
    int bColT = (tid & 15) * 4;

    for (int k0 = 0; k0 < K; k0 += 16) {
        float4 av = make_float4(0.f, 0.f, 0.f, 0.f);
        if (aRow < N)
            av = *reinterpret_cast<const float4*>(A + (size_t)aRow * K + k0 + aColT);
        As[aColT + 0][tid >> 2] = av.x;
        As[aColT + 1][tid >> 2] = av.y;
        As[aColT + 2][tid >> 2] = av.z;
        As[aColT + 3][tid >> 2] = av.w;
        float4 bv = *reinterpret_cast<const float4*>(B + (size_t)(k0 + bRowT) * M + colBase + bColT);
        *reinterpret_cast<float4*>(&Bs[bRowT][bColT]) = bv;
        __syncthreads();
#pragma unroll
        for (int k = 0; k < 16; k++) {
            float a[4], b[4];
#pragma unroll
            for (int i = 0; i < 4; i++) a[i] = As[k][ty * 4 + i];
#pragma unroll
            for (int j = 0; j < 4; j++) b[j] = Bs[k][tx * 4 + j];
#pragma unroll
            for (int i = 0; i < 4; i++)
#pragma unroll
                for (int j = 0; j < 4; j++) acc[i][j] += a[i] * b[j];
        }
        __syncthreads();
    }

#pragma unroll
    for (int i = 0; i < 4; i++) {
        int r = rowBase + ty * 4 + i;
        if (r >= N) continue;
#pragma unroll
        for (int j = 0; j < 4; j++) {
            int c = colBase + tx * 4 + j;
            float v = acc[i][j];
            if (bias) v += bias[c];
            if (doRelu) v = fmaxf(v, 0.f);
            C[(size_t)r * M + c] = v;
        }
    }
}

// ---------------- self-loop init: acc[i] = feat[i] * dinv[i]^2 --------------
__global__ void self_init(const float* __restrict__ feat, float* __restrict__ acc,
                          int n, int F) {
    size_t idx = (size_t)blockIdx.x * blockDim.x + threadIdx.x;
    if (idx >= (size_t)n * F) return;
    float di = g_dinv[idx / F];
    acc[idx] = feat[idx] * di * di;
}

// ---------------- edge scatter, 128-wide: warp per edge, v4 red -------------
__global__ __launch_bounds__(256) void scatter128(
    const float* __restrict__ feat, float* __restrict__ acc,
    const int* __restrict__ src, const int* __restrict__ dst, int e)
{
    int eid = (blockIdx.x * blockDim.x + threadIdx.x) >> 5;
    if (eid >= e) return;
    int lane = threadIdx.x & 31;
    int s = src[eid], d = dst[eid];
    float w = g_dinv[s] * g_dinv[d];
    float4 v = *(reinterpret_cast<const float4*>(feat + (size_t)s * 128) + lane);
    v.x *= w; v.y *= w; v.z *= w; v.w *= w;
    float* out = acc + (size_t)d * 128 + lane * 4;
    asm volatile("red.global.add.v4.f32 [%0], {%1,%2,%3,%4};"
                 :: "l"(out), "f"(v.x), "f"(v.y), "f"(v.z), "f"(v.w) : "memory");
}

// ---------------- edge scatter, 64-wide: warp per edge, v2 red --------------
__global__ __launch_bounds__(256) void scatter64(
    const float* __restrict__ feat, float* __restrict__ acc,
    const int* __restrict__ src, const int* __restrict__ dst, int e)
{
    int eid = (blockIdx.x * blockDim.x + threadIdx.x) >> 5;
    if (eid >= e) return;
    int lane = threadIdx.x & 31;
    int s = src[eid], d = dst[eid];
    float w = g_dinv[s] * g_dinv[d];
    float2 v = *(reinterpret_cast<const float2*>(feat + (size_t)s * 64) + lane);
    v.x *= w; v.y *= w;
    float* out = acc + (size_t)d * 64 + lane * 2;
    asm volatile("red.global.add.v2.f32 [%0], {%1,%2};"
                 :: "l"(out), "f"(v.x), "f"(v.y) : "memory");
}

// ---------------- h = relu(acc + b1); acc <- h * dinv^2 (ah self-loop) ------
__global__ void fuse_h(const float* __restrict__ b1, int n) {
    size_t idx = (size_t)blockIdx.x * blockDim.x + threadIdx.x;
    if (idx >= (size_t)n * 128) return;
    float v = g_acc[idx] + b1[idx & 127];
    v = fmaxf(v, 0.f);
    g_h[idx] = v;
    float di = g_dinv[idx >> 7];
    g_acc[idx] = v * di * di;
}

// ---------------- z = eps*exp(0.5*lv)+mu; az_init = z*dinv^2 ----------------
__global__ void make_z(const float* __restrict__ mu, const float* __restrict__ lv,
                       const float* __restrict__ eps, float* __restrict__ z, int n) {
    size_t idx = (size_t)blockIdx.x * blockDim.x + threadIdx.x;
    if (idx >= (size_t)n * 64) return;
    float zz = eps[idx] * expf(0.5f * lv[idx]) + mu[idx];
    z[idx] = zz;
    float di = g_dinv[idx >> 6];
    g_az[idx] = zz * di * di;
}

// ---------------- heads: gender (gumbel) + logits_label, warp per node ------
__global__ __launch_bounds__(256) void heads(
    const float* __restrict__ z, const float* __restrict__ u,
    const float* __restrict__ Wg, const float* __restrict__ bg,
    const float* __restrict__ Wlc, const float* __restrict__ blc,
    float* __restrict__ gender, float* __restrict__ label, int n)
{
    int node = (blockIdx.x * blockDim.x + threadIdx.x) >> 5;
    if (node >= n) return;
    int lane = threadIdx.x & 31;
    float2 a  = *(reinterpret_cast<const float2*>(g_az + (size_t)node * 64) + lane);
    float2 zz = *(reinterpret_cast<const float2*>(z + (size_t)node * 64) + lane);
    int k = lane * 2;
    // Wg: [64,2] row-major, Wlc: [64,1]
    float p0 = a.x * Wg[k * 2 + 0] + a.y * Wg[(k + 1) * 2 + 0];
    float p1 = a.x * Wg[k * 2 + 1] + a.y * Wg[(k + 1) * 2 + 1];
    float pl = zz.x * Wlc[k] + zz.y * Wlc[k + 1];
#pragma unroll
    for (int off = 16; off; off >>= 1) {
        p0 += __shfl_xor_sync(0xffffffffu, p0, off);
        p1 += __shfl_xor_sync(0xffffffffu, p1, off);
        pl += __shfl_xor_sync(0xffffffffu, pl, off);
    }
    if (lane == 0) {
        float l0 = p0 + bg[0], l1 = p1 + bg[1];
        float u0 = u[(size_t)node * 2], u1 = u[(size_t)node * 2 + 1];
        float gn0 = -logf(-logf(u0 + 1e-20f) + 1e-20f);
        float gn1 = -logf(-logf(u1 + 1e-20f) + 1e-20f);
        float a0 = l0 + gn0, a1 = l1 + gn1;
        float m = fmaxf(a0, a1);
        float e0 = expf(a0 - m), e1 = expf(a1 - m);
        float inv = 1.0f / (e0 + e1);
        float s0 = e0 * inv, s1 = e1 * inv;
        float h0 = (s0 >= s1) ? 1.0f : 0.0f;   // jnp.argmax picks first max
        float h1 = 1.0f - h0;
        gender[(size_t)node * 2 + 0] = (h0 - s0) + s0;
        gender[(size_t)node * 2 + 1] = (h1 - s1) + s1;
        label[node] = pl + blc[0];
    }
}

// ---------------- launch -----------------------------------------------------
extern "C" void kernel_launch(void* const* d_in, const int* in_sizes, int n_in,
                              void* d_out, int out_size) {
    const float* x   = (const float*)d_in[0];
    const int*   ei  = (const int*)d_in[1];
    const float* eps = (const float*)d_in[2];
    const float* u   = (const float*)d_in[3];
    const float* W1  = (const float*)d_in[4];
    const float* b1  = (const float*)d_in[5];
    const float* Wmu = (const float*)d_in[6];
    const float* bmu = (const float*)d_in[7];
    const float* Wls = (const float*)d_in[8];
    const float* bls = (const float*)d_in[9];
    const float* Wdx = (const float*)d_in[10];
    const float* bdx = (const float*)d_in[11];
    const float* Wg  = (const float*)d_in[12];
    const float* bg  = (const float*)d_in[13];
    const float* Wlc = (const float*)d_in[14];
    const float* blc = (const float*)d_in[15];

    const int N = in_sizes[0] / 128;
    const int E = in_sizes[1] / 2;
    const int* src = ei;
    const int* dst = ei + E;

    float* out    = (float*)d_out;
    float* recon  = out;                                // [N,128]
    float* gender = out + (size_t)N * 128;              // [N,2]
    float* label  = gender + (size_t)N * 2;             // [N,1]
    float* mu     = label + N;                          // [N,64]
    float* lv     = mu + (size_t)N * 64;                // [N,64]
    float* z      = lv + (size_t)N * 64;                // [N,64]

    float *p_t, *p_acc, *p_h, *p_az;
    cudaGetSymbolAddress((void**)&p_t, g_t);
    cudaGetSymbolAddress((void**)&p_acc, g_acc);
    cudaGetSymbolAddress((void**)&p_h, g_h);
    cudaGetSymbolAddress((void**)&p_az, g_az);

    const int T = 256;
    // 1) degree / norm
    deg_init<<<(N + T - 1) / T, T>>>(N);
    deg_count<<<(E + T - 1) / T, T>>>(dst, E);
    deg_finish<<<(N + T - 1) / T, T>>>(N);

    // 2) t = x @ W1 (no bias; bias applied post-aggregation)
    dim3 g128((128 + 63) / 64, (N + 63) / 64);
    dim3 g64x((64 + 63) / 64, (N + 63) / 64);
    sgemm_bias<<<g128, 256>>>(x, W1, nullptr, p_t, N, 128, 128, 0);

    // 3) acc = A_norm @ t  (self loops + edges)
    size_t n128 = (size_t)N * 128;
    self_init<<<(int)((n128 + T - 1) / T), T>>>(p_t, p_acc, N, 128);
    scatter128<<<(int)(((size_t)E * 32 + T - 1) / T), T>>>(p_t, p_acc, src, dst, E);

    // 4) h = relu(acc + b1); acc <- h * dinv^2 (self-loop for next agg)
    fuse_h<<<(int)((n128 + T - 1) / T), T>>>(b1, N);

    // 5) acc = A_norm @ h
    scatter128<<<(int)(((size_t)E * 32 + T - 1) / T), T>>>(p_h, p_acc, src, dst, E);

    // 6) mu, logvar = acc @ {Wmu, Wls} + bias
    sgemm_bias<<<g64x, 256>>>(p_acc, Wmu, bmu, mu, N, 128, 64, 0);
    sgemm_bias<<<g64x, 256>>>(p_acc, Wls, bls, lv, N, 128, 64, 0);

    // 7) z + az self-loop init
    size_t n64 = (size_t)N * 64;
    make_z<<<(int)((n64 + T - 1) / T), T>>>(mu, lv, eps, z, N);

    // 8) az = A_norm @ z
    scatter64<<<(int)(((size_t)E * 32 + T - 1) / T), T>>>(z, p_az, src, dst, E);

    // 9) recon_x = az @ Wdx + bdx
    sgemm_bias<<<g128, 256>>>(p_az, Wdx, bdx, recon, N, 64, 128, 0);

    // 10) gender (gumbel) + logits_label
    heads<<<(int)(((size_t)N * 32 + T - 1) / T), T>>>(z, u, Wg, bg, Wlc, blc,
                                                      gender, label, N);
}

// round 2
// speedup vs baseline: 1.8261x; 1.8261x over previous
#include <cuda_runtime.h>
#include <cuda_bf16.h>
#include <math.h>

#define NMAX 50048
#define EMAX 1700000

// ---------------- scratch (device globals) ----------------------------------
__device__ float g_t[(size_t)NMAX * 128];    // x@W1
__device__ float g_acc[(size_t)NMAX * 128];  // aggregated h
__device__ float g_h[(size_t)NMAX * 128];    // hidden after relu
__device__ float g_muls[(size_t)NMAX * 128]; // packed [mu | logvar]
__device__ float g_az[(size_t)NMAX * 64];    // aggregated z
__device__ float g_dinv[NMAX];               // deg^-0.5
__device__ int   g_cnt[NMAX];                // in-degree (real edges)
__device__ int   g_off[NMAX];                // CSR row offsets
__device__ int   g_cur[NMAX];                // fill cursors
__device__ int   g_csrc[EMAX];               // CSR src ids
__device__ float g_cw[EMAX];                 // CSR edge weights
__device__ float g_wpack[128 * 128];         // [Wmu | Wls]
__device__ float g_bpack[128];               // [bmu | bls]

// ---------------- degree / CSR build ----------------------------------------
__global__ void cnt_zero(int n) {
    int i = blockIdx.x * blockDim.x + threadIdx.x;
    if (i < n) { g_cnt[i] = 0; g_cur[i] = 0; }
}
__global__ void cnt_count(const int* __restrict__ dst, int e) {
    int i = blockIdx.x * blockDim.x + threadIdx.x;
    if (i < e) atomicAdd(&g_cnt[dst[i]], 1);
}
__global__ void dinv_fin(int n) {
    int i = blockIdx.x * blockDim.x + threadIdx.x;
    if (i < n) g_dinv[i] = rsqrtf(1.0f + (float)g_cnt[i]);  // +1 self loop
}
// single-block exclusive scan of g_cnt -> g_off (n <= 1024*chunk)
__global__ __launch_bounds__(1024) void scan_offsets(int n) {
    __shared__ int part[1024];
    int tid = threadIdx.x;
    int chunk = (n + 1023) >> 10;
    int beg = tid * chunk;
    int end = min(beg + chunk, n);
    int s = 0;
    for (int i = beg; i < end; i++) s += g_cnt[i];
    part[tid] = s;
    __syncthreads();
    for (int off = 1; off < 1024; off <<= 1) {
        int v = (tid >= off) ? part[tid - off] : 0;
        __syncthreads();
        part[tid] += v;
        __syncthreads();
    }
    int base = (tid > 0) ? part[tid - 1] : 0;
    for (int i = beg; i < end; i++) { g_off[i] = base; base += g_cnt[i]; }
}
__global__ void csr_fill(const int* __restrict__ src, const int* __restrict__ dst, int e) {
    int i = blockIdx.x * blockDim.x + threadIdx.x;
    if (i >= e) return;
    int s = src[i], d = dst[i];
    int pos = g_off[d] + atomicAdd(&g_cur[d], 1);
    g_csrc[pos] = s;
    g_cw[pos] = g_dinv[s] * g_dinv[d];
}

// ---------------- aggregation: warp per node, 128-wide -----------------------
__global__ __launch_bounds__(256) void agg128(
    const float* __restrict__ feat, float* __restrict__ out,
    const float* __restrict__ bias, int doRelu, int n)
{
    int node = (blockIdx.x * blockDim.x + threadIdx.x) >> 5;
    if (node >= n) return;
    int lane = threadIdx.x & 31;
    float di = g_dinv[node];
    float w0 = di * di;
    float4 self = __ldg(reinterpret_cast<const float4*>(feat + (size_t)node * 128) + lane);
    float4 acc = make_float4(self.x * w0, self.y * w0, self.z * w0, self.w * w0);

    int j = g_off[node];
    int jend = j + g_cnt[node];
    for (; j + 4 <= jend; j += 4) {
        int s0 = g_csrc[j], s1 = g_csrc[j + 1], s2 = g_csrc[j + 2], s3 = g_csrc[j + 3];
        float w0_ = g_cw[j], w1_ = g_cw[j + 1], w2_ = g_cw[j + 2], w3_ = g_cw[j + 3];
        float4 v0 = __ldg(reinterpret_cast<const float4*>(feat + (size_t)s0 * 128) + lane);
        float4 v1 = __ldg(reinterpret_cast<const float4*>(feat + (size_t)s1 * 128) + lane);
        float4 v2 = __ldg(reinterpret_cast<const float4*>(feat + (size_t)s2 * 128) + lane);
        float4 v3 = __ldg(reinterpret_cast<const float4*>(feat + (size_t)s3 * 128) + lane);
        acc.x += w0_ * v0.x; acc.y += w0_ * v0.y; acc.z += w0_ * v0.z; acc.w += w0_ * v0.w;
        acc.x += w1_ * v1.x; acc.y += w1_ * v1.y; acc.z += w1_ * v1.z; acc.w += w1_ * v1.w;
        acc.x += w2_ * v2.x; acc.y += w2_ * v2.y; acc.z += w2_ * v2.z; acc.w += w2_ * v2.w;
        acc.x += w3_ * v3.x; acc.y += w3_ * v3.y; acc.z += w3_ * v3.z; acc.w += w3_ * v3.w;
    }
    for (; j < jend; j++) {
        int s = g_csrc[j];
        float w = g_cw[j];
        float4 v = __ldg(reinterpret_cast<const float4*>(feat + (size_t)s * 128) + lane);
        acc.x += w * v.x; acc.y += w * v.y; acc.z += w * v.z; acc.w += w * v.w;
    }
    if (bias) {
        float4 b = __ldg(reinterpret_cast<const float4*>(bias) + lane);
        acc.x += b.x; acc.y += b.y; acc.z += b.z; acc.w += b.w;
    }
    if (doRelu) {
        acc.x = fmaxf(acc.x, 0.f); acc.y = fmaxf(acc.y, 0.f);
        acc.z = fmaxf(acc.z, 0.f); acc.w = fmaxf(acc.w, 0.f);
    }
    *(reinterpret_cast<float4*>(out + (size_t)node * 128) + lane) = acc;
}

// ---------------- aggregation: warp per node, 64-wide ------------------------
__global__ __launch_bounds__(256) void agg64(
    const float* __restrict__ feat, float* __restrict__ out, int n)
{
    int node = (blockIdx.x * blockDim.x + threadIdx.x) >> 5;
    if (node >= n) return;
    int lane = threadIdx.x & 31;
    float di = g_dinv[node];
    float w0 = di * di;
    float2 self = __ldg(reinterpret_cast<const float2*>(feat + (size_t)node * 64) + lane);
    float2 acc = make_float2(self.x * w0, self.y * w0);

    int j = g_off[node];
    int jend = j + g_cnt[node];
    for (; j + 4 <= jend; j += 4) {
        int s0 = g_csrc[j], s1 = g_csrc[j + 1], s2 = g_csrc[j + 2], s3 = g_csrc[j + 3];
        float w0_ = g_cw[j], w1_ = g_cw[j + 1], w2_ = g_cw[j + 2], w3_ = g_cw[j + 3];
        float2 v0 = __ldg(reinterpret_cast<const float2*>(feat + (size_t)s0 * 64) + lane);
        float2 v1 = __ldg(reinterpret_cast<const float2*>(feat + (size_t)s1 * 64) + lane);
        float2 v2 = __ldg(reinterpret_cast<const float2*>(feat + (size_t)s2 * 64) + lane);
        float2 v3 = __ldg(reinterpret_cast<const float2*>(feat + (size_t)s3 * 64) + lane);
        acc.x += w0_ * v0.x; acc.y += w0_ * v0.y;
        acc.x += w1_ * v1.x; acc.y += w1_ * v1.y;
        acc.x += w2_ * v2.x; acc.y += w2_ * v2.y;
        acc.x += w3_ * v3.x; acc.y += w3_ * v3.y;
    }
    for (; j < jend; j++) {
        int s = g_csrc[j];
        float w = g_cw[j];
        float2 v = __ldg(reinterpret_cast<const float2*>(feat + (size_t)s * 64) + lane);
        acc.x += w * v.x; acc.y += w * v.y;
    }
    *(reinterpret_cast<float2*>(out + (size_t)node * 64) + lane) = acc;
}

// ---------------- fp32 GEMM: 128x128 tile, 8x8 microtile, BK=8 ---------------
// C[N,M] = A[N,K] @ B[K,M] + bias. Requires M == 128, K % 8 == 0.
__global__ __launch_bounds__(256) void sgemm128(
    const float* __restrict__ A, const float* __restrict__ B,
    const float* __restrict__ bias, float* __restrict__ C, int N, int K)
{
    const int M = 128;
    __shared__ float As[8][128];
    __shared__ float Bs[8][128];
    int tid = threadIdx.x;
    int row0 = blockIdx.y * 128;

    int ar = tid >> 1, ak = (tid & 1) * 4;   // A: 128 rows x 8k
    int br = tid >> 5, bc = (tid & 31) * 4;  // B: 8 rows x 128 cols
    int ty = tid >> 4, tx = tid & 15;        // 16x16 thread grid

    float acc[8][8];
#pragma unroll
    for (int i = 0; i < 8; i++)
#pragma unroll
        for (int j = 0; j < 8; j++) acc[i][j] = 0.f;

    for (int k0 = 0; k0 < K; k0 += 8) {
        float4 av = make_float4(0.f, 0.f, 0.f, 0.f);
        if (row0 + ar < N)
            av = *reinterpret_cast<const float4*>(A + (size_t)(row0 + ar) * K + k0 + ak);
        As[ak + 0][ar] = av.x;
        As[ak + 1][ar] = av.y;
        As[ak + 2][ar] = av.z;
        As[ak + 3][ar] = av.w;
        float4 bv = *reinterpret_cast<const float4*>(B + (size_t)(k0 + br) * M + bc);
        *reinterpret_cast<float4*>(&Bs[br][bc]) = bv;
        __syncthreads();
#pragma unroll
        for (int kk = 0; kk < 8; kk++) {
            float a[8], b[8];
#pragma unroll
            for (int i = 0; i < 4; i++) {
                a[i]     = As[kk][ty * 8 + i];
                a[i + 4] = As[kk][ty * 8 + 4 + i];
                b[i]     = Bs[kk][tx * 8 + i];
                b[i + 4] = Bs[kk][tx * 8 + 4 + i];
            }
#pragma unroll
            for (int i = 0; i < 8; i++)
#pragma unroll
                for (int j = 0; j < 8; j++) acc[i][j] += a[i] * b[j];
        }
        __syncthreads();
    }

    float bvals[8];
#pragma unroll
    for (int j = 0; j < 8; j++) bvals[j] = bias ? bias[tx * 8 + j] : 0.f;
#pragma unroll
    for (int i = 0; i < 8; i++) {
        int r = row0 + ty * 8 + i;
        if (r >= N) continue;
        float4 lo = make_float4(acc[i][0] + bvals[0], acc[i][1] + bvals[1],
                                acc[i][2] + bvals[2], acc[i][3] + bvals[3]);
        float4 hi = make_float4(acc[i][4] + bvals[4], acc[i][5] + bvals[5],
                                acc[i][6] + bvals[6], acc[i][7] + bvals[7]);
        *reinterpret_cast<float4*>(C + (size_t)r * M + tx * 8) = lo;
        *reinterpret_cast<float4*>(C + (size_t)r * M + tx * 8 + 4) = hi;
    }
}

// ---------------- pack [Wmu | Wls] into one 128x128 weight -------------------
__global__ void pack_w(const float* __restrict__ Wmu, const float* __restrict__ Wls,
                       const float* __restrict__ bmu, const float* __restrict__ bls)
{
    int idx = blockIdx.x * blockDim.x + threadIdx.x;
    if (idx >= 128 * 64) return;
    int row = idx >> 6, col = idx & 63;
    g_wpack[row * 128 + col]      = Wmu[row * 64 + col];
    g_wpack[row * 128 + 64 + col] = Wls[row * 64 + col];
    if (idx < 64) { g_bpack[idx] = bmu[idx]; g_bpack[64 + idx] = bls[idx]; }
}

// ---------------- z = eps*exp(0.5*lv)+mu; copy mu/lv to out ------------------
__global__ void make_z(const float* __restrict__ eps,
                       float* __restrict__ mu_o, float* __restrict__ lv_o,
                       float* __restrict__ z_o, int n)
{
    size_t idx = (size_t)blockIdx.x * blockDim.x + threadIdx.x;
    if (idx >= (size_t)n * 64) return;
    size_t row = idx >> 6;
    int col = (int)(idx & 63);
    float mu = g_muls[row * 128 + col];
    float lv = g_muls[row * 128 + 64 + col];
    mu_o[idx] = mu;
    lv_o[idx] = lv;
    z_o[idx] = eps[idx] * expf(0.5f * lv) + mu;
}

// ---------------- heads: gender (gumbel) + logits_label ----------------------
__global__ __launch_bounds__(256) void heads(
    const float* __restrict__ z, const float* __restrict__ u,
    const float* __restrict__ Wg, const float* __restrict__ bg,
    const float* __restrict__ Wlc, const float* __restrict__ blc,
    float* __restrict__ gender, float* __restrict__ label, int n)
{
    int node = (blockIdx.x * blockDim.x + threadIdx.x) >> 5;
    if (node >= n) return;
    int lane = threadIdx.x & 31;
    float2 a  = *(reinterpret_cast<const float2*>(g_az + (size_t)node * 64) + lane);
    float2 zz = __ldg(reinterpret_cast<const float2*>(z + (size_t)node * 64) + lane);
    int k = lane * 2;
    float p0 = a.x * Wg[k * 2 + 0] + a.y * Wg[(k + 1) * 2 + 0];
    float p1 = a.x * Wg[k * 2 + 1] + a.y * Wg[(k + 1) * 2 + 1];
    float pl = zz.x * Wlc[k] + zz.y * Wlc[k + 1];
#pragma unroll
    for (int off = 16; off; off >>= 1) {
        p0 += __shfl_xor_sync(0xffffffffu, p0, off);
        p1 += __shfl_xor_sync(0xffffffffu, p1, off);
        pl += __shfl_xor_sync(0xffffffffu, pl, off);
    }
    if (lane == 0) {
        float l0 = p0 + bg[0], l1 = p1 + bg[1];
        float u0 = u[(size_t)node * 2], u1 = u[(size_t)node * 2 + 1];
        float gn0 = -logf(-logf(u0 + 1e-20f) + 1e-20f);
        float gn1 = -logf(-logf(u1 + 1e-20f) + 1e-20f);
        float a0 = l0 + gn0, a1 = l1 + gn1;
        float m = fmaxf(a0, a1);
        float e0 = expf(a0 - m), e1 = expf(a1 - m);
        float inv = 1.0f / (e0 + e1);
        float s0 = e0 * inv, s1 = e1 * inv;
        float h0 = (s0 >= s1) ? 1.0f : 0.0f;
        float h1 = 1.0f - h0;
        gender[(size_t)node * 2 + 0] = (h0 - s0) + s0;
        gender[(size_t)node * 2 + 1] = (h1 - s1) + s1;
        label[node] = pl + blc[0];
    }
}

// ---------------- launch -----------------------------------------------------
extern "C" void kernel_launch(void* const* d_in, const int* in_sizes, int n_in,
                              void* d_out, int out_size) {
    const float* x   = (const float*)d_in[0];
    const int*   ei  = (const int*)d_in[1];
    const float* eps = (const float*)d_in[2];
    const float* u   = (const float*)d_in[3];
    const float* W1  = (const float*)d_in[4];
    const float* b1  = (const float*)d_in[5];
    const float* Wmu = (const float*)d_in[6];
    const float* bmu = (const float*)d_in[7];
    const float* Wls = (const float*)d_in[8];
    const float* bls = (const float*)d_in[9];
    const float* Wdx = (const float*)d_in[10];
    const float* bdx = (const float*)d_in[11];
    const float* Wg  = (const float*)d_in[12];
    const float* bg  = (const float*)d_in[13];
    const float* Wlc = (const float*)d_in[14];
    const float* blc = (const float*)d_in[15];

    const int N = in_sizes[0] / 128;
    const int E = in_sizes[1] / 2;
    const int* src = ei;
    const int* dst = ei + E;

    float* out    = (float*)d_out;
    float* recon  = out;                     // [N,128]
    float* gender = out + (size_t)N * 128;   // [N,2]
    float* label  = gender + (size_t)N * 2;  // [N,1]
    float* mu     = label + N;               // [N,64]
    float* lv     = mu + (size_t)N * 64;     // [N,64]
    float* z      = lv + (size_t)N * 64;     // [N,64]

    float *p_t, *p_acc, *p_h, *p_az, *p_wpack, *p_bpack;
    cudaGetSymbolAddress((void**)&p_t, g_t);
    cudaGetSymbolAddress((void**)&p_acc, g_acc);
    cudaGetSymbolAddress((void**)&p_h, g_h);
    cudaGetSymbolAddress((void**)&p_az, g_az);
    cudaGetSymbolAddress((void**)&p_wpack, g_wpack);
    cudaGetSymbolAddress((void**)&p_bpack, g_bpack);

    const int T = 256;
    int nodeWarpBlocks = (int)(((size_t)N * 32 + T - 1) / T);

    // 1) CSR build
    cnt_zero<<<(N + T - 1) / T, T>>>(N);
    cnt_count<<<(E + T - 1) / T, T>>>(dst, E);
    dinv_fin<<<(N + T - 1) / T, T>>>(N);
    scan_offsets<<<1, 1024>>>(N);
    csr_fill<<<(E + T - 1) / T, T>>>(src, dst, E);

    // 2) t = x @ W1  (bias folded into agg epilogue)
    dim3 gg(1, (N + 127) / 128);
    sgemm128<<<gg, 256>>>(x, W1, nullptr, p_t, N, 128);

    // 3) h = relu(A_norm @ t + b1)
    agg128<<<nodeWarpBlocks, T>>>(p_t, p_h, b1, 1, N);

    // 4) ah = A_norm @ h
    agg128<<<nodeWarpBlocks, T>>>(p_h, p_acc, nullptr, 0, N);

    // 5) [mu | logvar] = ah @ [Wmu|Wls] + [bmu|bls]   (one fused GEMM)
    pack_w<<<(128 * 64 + T - 1) / T, T>>>(Wmu, Wls, bmu, bls);
    float* p_muls;
    cudaGetSymbolAddress((void**)&p_muls, g_muls);
    sgemm128<<<gg, 256>>>(p_acc, p_wpack, p_bpack, p_muls, N, 128);

    // 6) z = eps*exp(0.5*logvar)+mu; copy mu/lv to out
    size_t n64 = (size_t)N * 64;
    make_z<<<(int)((n64 + T - 1) / T), T>>>(eps, mu, lv, z, N);

    // 7) az = A_norm @ z
    agg64<<<nodeWarpBlocks, T>>>(z, p_az, N);

    // 8) recon_x = az @ Wdx + bdx
    sgemm128<<<gg, 256>>>(p_az, Wdx, bdx, recon, N, 64);

    // 9) gender (gumbel) + logits_label
    heads<<<nodeWarpBlocks, T>>>(z, u, Wg, bg, Wlc, blc, gender, label, N);
}

// round 3
// speedup vs baseline: 2.1407x; 1.1722x over previous
#include <cuda_runtime.h>
#include <cuda_fp16.h>
#include <cuda_bf16.h>
#include <math.h>

#define NMAX 50048
#define EMAX 1700000
#define NBLK ((NMAX + 1023) / 1024)

// ---------------- scratch (device globals) ----------------------------------
__device__ __half g_tb[(size_t)NMAX * 128];  // x@W1 (fp16 gather table)
__device__ __half g_hb[(size_t)NMAX * 128];  // hidden after relu (fp16 table)
__device__ float g_acc[(size_t)NMAX * 128];  // aggregated h (fp32)
__device__ float g_muls[(size_t)NMAX * 128]; // packed [mu | logvar]
__device__ float g_az[(size_t)NMAX * 64];    // aggregated z
__device__ float g_dinv[NMAX];               // deg^-0.5
__device__ int   g_cnt[NMAX];                // in-degree (real edges)
__device__ int   g_off[NMAX];                // CSR row offsets
__device__ int   g_cur[NMAX];                // fill cursors
__device__ int   g_bsum[NBLK];               // scan block sums
__device__ int   g_csrc[EMAX];               // CSR src ids
__device__ float g_cw[EMAX];                 // CSR edge weights
__device__ float g_wpack[128 * 128];         // [Wmu | Wls]
__device__ float g_bpack[128];               // [bmu | bls]

// ---------------- degree / CSR build ----------------------------------------
__global__ void cnt_zero(int n) {
    int i = blockIdx.x * blockDim.x + threadIdx.x;
    if (i < n) { g_cnt[i] = 0; g_cur[i] = 0; }
}
__global__ void cnt_count(const int* __restrict__ dst, int e) {
    int i = blockIdx.x * blockDim.x + threadIdx.x;
    if (i < e) atomicAdd(&g_cnt[dst[i]], 1);
}
__global__ void dinv_fin(int n) {
    int i = blockIdx.x * blockDim.x + threadIdx.x;
    if (i < n) g_dinv[i] = rsqrtf(1.0f + (float)g_cnt[i]);  // +1 self loop
}

// ---------------- parallel 3-phase scan --------------------------------------
__global__ __launch_bounds__(1024) void scan_blocks(int n) {
    __shared__ int sh[1024];
    int tid = threadIdx.x;
    int i = blockIdx.x * 1024 + tid;
    int v = (i < n) ? g_cnt[i] : 0;
    sh[tid] = v;
    __syncthreads();
#pragma unroll
    for (int off = 1; off < 1024; off <<= 1) {
        int t = (tid >= off) ? sh[tid - off] : 0;
        __syncthreads();
        sh[tid] += t;
        __syncthreads();
    }
    if (i < n) g_off[i] = sh[tid] - v;  // exclusive within block
    if (tid == 1023) g_bsum[blockIdx.x] = sh[1023];
}
__global__ __launch_bounds__(64) void scan_bsum(int nb) {
    __shared__ int sh[64];
    int tid = threadIdx.x;
    int v = (tid < nb) ? g_bsum[tid] : 0;
    sh[tid] = v;
    __syncthreads();
#pragma unroll
    for (int off = 1; off < 64; off <<= 1) {
        int t = (tid >= off) ? sh[tid - off] : 0;
        __syncthreads();
        sh[tid] += t;
        __syncthreads();
    }
    if (tid < nb) g_bsum[tid] = sh[tid] - v;  // exclusive
}
__global__ void add_bsum(int n) {
    int i = blockIdx.x * blockDim.x + threadIdx.x;
    if (i < n) g_off[i] += g_bsum[i >> 10];
}
__global__ void csr_fill(const int* __restrict__ src, const int* __restrict__ dst, int e) {
    int i = blockIdx.x * blockDim.x + threadIdx.x;
    if (i >= e) return;
    int s = src[i], d = dst[i];
    int pos = g_off[d] + atomicAdd(&g_cur[d], 1);
    g_csrc[pos] = s;
    g_cw[pos] = g_dinv[s] * g_dinv[d];
}

// ---------------- fp16 gather helpers ----------------------------------------
__device__ __forceinline__ void acc_h4(float4& acc, uint2 q, float w) {
    __half2 p0 = *reinterpret_cast<__half2*>(&q.x);
    __half2 p1 = *reinterpret_cast<__half2*>(&q.y);
    float2 f0 = __half22float2(p0);
    float2 f1 = __half22float2(p1);
    acc.x += w * f0.x; acc.y += w * f0.y;
    acc.z += w * f1.x; acc.w += w * f1.y;
}

// ---------------- aggregation: warp per node, 128-wide, fp16 table -----------
// out: either fp16 table (outh) or fp32 (outf); one must be non-null.
__global__ __launch_bounds__(256) void agg128h(
    const __half* __restrict__ feat, __half* __restrict__ outh,
    float* __restrict__ outf, const float* __restrict__ bias, int doRelu, int n)
{
    int node = (blockIdx.x * blockDim.x + threadIdx.x) >> 5;
    if (node >= n) return;
    int lane = threadIdx.x & 31;
    const uint2* fb = reinterpret_cast<const uint2*>(feat);  // 32 uint2 per row

    float di = g_dinv[node];
    float w0 = di * di;
    float4 acc = make_float4(0.f, 0.f, 0.f, 0.f);
    acc_h4(acc, __ldg(fb + (size_t)node * 32 + lane), w0);

    int j = g_off[node];
    int jend = j + g_cnt[node];
    for (; j + 4 <= jend; j += 4) {
        int s0 = g_csrc[j], s1 = g_csrc[j + 1], s2 = g_csrc[j + 2], s3 = g_csrc[j + 3];
        float wa = g_cw[j], wb = g_cw[j + 1], wc = g_cw[j + 2], wd = g_cw[j + 3];
        uint2 q0 = __ldg(fb + (size_t)s0 * 32 + lane);
        uint2 q1 = __ldg(fb + (size_t)s1 * 32 + lane);
        uint2 q2 = __ldg(fb + (size_t)s2 * 32 + lane);
        uint2 q3 = __ldg(fb + (size_t)s3 * 32 + lane);
        acc_h4(acc, q0, wa);
        acc_h4(acc, q1, wb);
        acc_h4(acc, q2, wc);
        acc_h4(acc, q3, wd);
    }
    for (; j < jend; j++) {
        acc_h4(acc, __ldg(fb + (size_t)g_csrc[j] * 32 + lane), g_cw[j]);
    }
    if (bias) {
        float4 b = __ldg(reinterpret_cast<const float4*>(bias) + lane);
        acc.x += b.x; acc.y += b.y; acc.z += b.z; acc.w += b.w;
    }
    if (doRelu) {
        acc.x = fmaxf(acc.x, 0.f); acc.y = fmaxf(acc.y, 0.f);
        acc.z = fmaxf(acc.z, 0.f); acc.w = fmaxf(acc.w, 0.f);
    }
    if (outh) {
        __half2 h0 = __floats2half2_rn(acc.x, acc.y);
        __half2 h1 = __floats2half2_rn(acc.z, acc.w);
        uint2 q;
        q.x = *reinterpret_cast<unsigned*>(&h0);
        q.y = *reinterpret_cast<unsigned*>(&h1);
        *(reinterpret_cast<uint2*>(outh) + (size_t)node * 32 + lane) = q;
    }
    if (outf) {
        *(reinterpret_cast<float4*>(outf + (size_t)node * 128) + lane) = acc;
    }
}

// ---------------- aggregation: warp per node, 64-wide, fp32 ------------------
__global__ __launch_bounds__(256) void agg64(
    const float* __restrict__ feat, float* __restrict__ out, int n)
{
    int node = (blockIdx.x * blockDim.x + threadIdx.x) >> 5;
    if (node >= n) return;
    int lane = threadIdx.x & 31;
    float di = g_dinv[node];
    float w0 = di * di;
    float2 self = __ldg(reinterpret_cast<const float2*>(feat + (size_t)node * 64) + lane);
    float2 acc = make_float2(self.x * w0, self.y * w0);

    int j = g_off[node];
    int jend = j + g_cnt[node];
    for (; j + 4 <= jend; j += 4) {
        int s0 = g_csrc[j], s1 = g_csrc[j + 1], s2 = g_csrc[j + 2], s3 = g_csrc[j + 3];
        float wa = g_cw[j], wb = g_cw[j + 1], wc = g_cw[j + 2], wd = g_cw[j + 3];
        float2 v0 = __ldg(reinterpret_cast<const float2*>(feat + (size_t)s0 * 64) + lane);
        float2 v1 = __ldg(reinterpret_cast<const float2*>(feat + (size_t)s1 * 64) + lane);
        float2 v2 = __ldg(reinterpret_cast<const float2*>(feat + (size_t)s2 * 64) + lane);
        float2 v3 = __ldg(reinterpret_cast<const float2*>(feat + (size_t)s3 * 64) + lane);
        acc.x += wa * v0.x; acc.y += wa * v0.y;
        acc.x += wb * v1.x; acc.y += wb * v1.y;
        acc.x += wc * v2.x; acc.y += wc * v2.y;
        acc.x += wd * v3.x; acc.y += wd * v3.y;
    }
    for (; j < jend; j++) {
        int s = g_csrc[j];
        float w = g_cw[j];
        float2 v = __ldg(reinterpret_cast<const float2*>(feat + (size_t)s * 64) + lane);
        acc.x += w * v.x; acc.y += w * v.y;
    }
    *(reinterpret_cast<float2*>(out + (size_t)node * 64) + lane) = acc;
}

// ---------------- fp32 GEMM: 128x128 tile, 8x8 microtile, BK=8 ---------------
// C[N,128] = A[N,K] @ B[K,128] + bias. fp32 out (C) and/or fp16 out (Ch).
__global__ __launch_bounds__(256) void sgemm128(
    const float* __restrict__ A, const float* __restrict__ B,
    const float* __restrict__ bias, float* __restrict__ C,
    __half* __restrict__ Ch, int N, int K)
{
    const int M = 128;
    __shared__ float As[8][128];
    __shared__ float Bs[8][128];
    int tid = threadIdx.x;
    int row0 = blockIdx.y * 128;

    int ar = tid >> 1, ak = (tid & 1) * 4;
    int br = tid >> 5, bc = (tid & 31) * 4;
    int ty = tid >> 4, tx = tid & 15;

    float acc[8][8];
#pragma unroll
    for (int i = 0; i < 8; i++)
#pragma unroll
        for (int j = 0; j < 8; j++) acc[i][j] = 0.f;

    for (int k0 = 0; k0 < K; k0 += 8) {
        float4 av = make_float4(0.f, 0.f, 0.f, 0.f);
        if (row0 + ar < N)
            av = *reinterpret_cast<const float4*>(A + (size_t)(row0 + ar) * K + k0 + ak);
        As[ak + 0][ar] = av.x;
        As[ak + 1][ar] = av.y;
        As[ak + 2][ar] = av.z;
        As[ak + 3][ar] = av.w;
        float4 bv = *reinterpret_cast<const float4*>(B + (size_t)(k0 + br) * M + bc);
        *reinterpret_cast<float4*>(&Bs[br][bc]) = bv;
        __syncthreads();
#pragma unroll
        for (int kk = 0; kk < 8; kk++) {
            float a[8], b[8];
#pragma unroll
            for (int i = 0; i < 4; i++) {
                a[i]     = As[kk][ty * 8 + i];
                a[i + 4] = As[kk][ty * 8 + 4 + i];
                b[i]     = Bs[kk][tx * 8 + i];
                b[i + 4] = Bs[kk][tx * 8 + 4 + i];
            }
#pragma unroll
            for (int i = 0; i < 8; i++)
#pragma unroll
                for (int j = 0; j < 8; j++) acc[i][j] += a[i] * b[j];
        }
        __syncthreads();
    }

    float bvals[8];
#pragma unroll
    for (int j = 0; j < 8; j++) bvals[j] = bias ? bias[tx * 8 + j] : 0.f;
#pragma unroll
    for (int i = 0; i < 8; i++) {
        int r = row0 + ty * 8 + i;
        if (r >= N) continue;
        float v[8];
#pragma unroll
        for (int j = 0; j < 8; j++) v[j] = acc[i][j] + bvals[j];
        if (C) {
            *reinterpret_cast<float4*>(C + (size_t)r * M + tx * 8) =
                make_float4(v[0], v[1], v[2], v[3]);
            *reinterpret_cast<float4*>(C + (size_t)r * M + tx * 8 + 4) =
                make_float4(v[4], v[5], v[6], v[7]);
        }
        if (Ch) {
            __half2 h0 = __floats2half2_rn(v[0], v[1]);
            __half2 h1 = __floats2half2_rn(v[2], v[3]);
            __half2 h2 = __floats2half2_rn(v[4], v[5]);
            __half2 h3 = __floats2half2_rn(v[6], v[7]);
            uint4 q;
            q.x = *reinterpret_cast<unsigned*>(&h0);
            q.y = *reinterpret_cast<unsigned*>(&h1);
            q.z = *reinterpret_cast<unsigned*>(&h2);
            q.w = *reinterpret_cast<unsigned*>(&h3);
            *reinterpret_cast<uint4*>(Ch + (size_t)r * M + tx * 8) = q;
        }
    }
}

// ---------------- pack [Wmu | Wls] into one 128x128 weight -------------------
__global__ void pack_w(const float* __restrict__ Wmu, const float* __restrict__ Wls,
                       const float* __restrict__ bmu, const float* __restrict__ bls)
{
    int idx = blockIdx.x * blockDim.x + threadIdx.x;
    if (idx >= 128 * 64) return;
    int row = idx >> 6, col = idx & 63;
    g_wpack[row * 128 + col]      = Wmu[row * 64 + col];
    g_wpack[row * 128 + 64 + col] = Wls[row * 64 + col];
    if (idx < 64) { g_bpack[idx] = bmu[idx]; g_bpack[64 + idx] = bls[idx]; }
}

// ---------------- z = eps*exp(0.5*lv)+mu; copy mu/lv to out ------------------
__global__ void make_z(const float* __restrict__ eps,
                       float* __restrict__ mu_o, float* __restrict__ lv_o,
                       float* __restrict__ z_o, int n)
{
    size_t idx = (size_t)blockIdx.x * blockDim.x + threadIdx.x;
    if (idx >= (size_t)n * 64) return;
    size_t row = idx >> 6;
    int col = (int)(idx & 63);
    float mu = g_muls[row * 128 + col];
    float lv = g_muls[row * 128 + 64 + col];
    mu_o[idx] = mu;
    lv_o[idx] = lv;
    z_o[idx] = eps[idx] * expf(0.5f * lv) + mu;
}

// ---------------- heads: gender (gumbel) + logits_label ----------------------
__global__ __launch_bounds__(256) void heads(
    const float* __restrict__ z, const float* __restrict__ u,
    const float* __restrict__ Wg, const float* __restrict__ bg,
    const float* __restrict__ Wlc, const float* __restrict__ blc,
    float* __restrict__ gender, float* __restrict__ label, int n)
{
    int node = (blockIdx.x * blockDim.x + threadIdx.x) >> 5;
    if (node >= n) return;
    int lane = threadIdx.x & 31;
    float2 a  = *(reinterpret_cast<const float2*>(g_az + (size_t)node * 64) + lane);
    float2 zz = __ldg(reinterpret_cast<const float2*>(z + (size_t)node * 64) + lane);
    int k = lane * 2;
    float p0 = a.x * Wg[k * 2 + 0] + a.y * Wg[(k + 1) * 2 + 0];
    float p1 = a.x * Wg[k * 2 + 1] + a.y * Wg[(k + 1) * 2 + 1];
    float pl = zz.x * Wlc[k] + zz.y * Wlc[k + 1];
#pragma unroll
    for (int off = 16; off; off >>= 1) {
        p0 += __shfl_xor_sync(0xffffffffu, p0, off);
        p1 += __shfl_xor_sync(0xffffffffu, p1, off);
        pl += __shfl_xor_sync(0xffffffffu, pl, off);
    }
    if (lane == 0) {
        float l0 = p0 + bg[0], l1 = p1 + bg[1];
        float u0 = u[(size_t)node * 2], u1 = u[(size_t)node * 2 + 1];
        float gn0 = -logf(-logf(u0 + 1e-20f) + 1e-20f);
        float gn1 = -logf(-logf(u1 + 1e-20f) + 1e-20f);
        float a0 = l0 + gn0, a1 = l1 + gn1;
        float m = fmaxf(a0, a1);
        float e0 = expf(a0 - m), e1 = expf(a1 - m);
        float inv = 1.0f / (e0 + e1);
        float s0 = e0 * inv, s1 = e1 * inv;
        float h0 = (s0 >= s1) ? 1.0f : 0.0f;
        float h1 = 1.0f - h0;
        gender[(size_t)node * 2 + 0] = (h0 - s0) + s0;
        gender[(size_t)node * 2 + 1] = (h1 - s1) + s1;
        label[node] = pl + blc[0];
    }
}

// ---------------- launch -----------------------------------------------------
extern "C" void kernel_launch(void* const* d_in, const int* in_sizes, int n_in,
                              void* d_out, int out_size) {
    const float* x   = (const float*)d_in[0];
    const int*   ei  = (const int*)d_in[1];
    const float* eps = (const float*)d_in[2];
    const float* u   = (const float*)d_in[3];
    const float* W1  = (const float*)d_in[4];
    const float* b1  = (const float*)d_in[5];
    const float* Wmu = (const float*)d_in[6];
    const float* bmu = (const float*)d_in[7];
    const float* Wls = (const float*)d_in[8];
    const float* bls = (const float*)d_in[9];
    const float* Wdx = (const float*)d_in[10];
    const float* bdx = (const float*)d_in[11];
    const float* Wg  = (const float*)d_in[12];
    const float* bg  = (const float*)d_in[13];
    const float* Wlc = (const float*)d_in[14];
    const float* blc = (const float*)d_in[15];

    const int N = in_sizes[0] / 128;
    const int E = in_sizes[1] / 2;
    const int* src = ei;
    const int* dst = ei + E;

    float* out    = (float*)d_out;
    float* recon  = out;                     // [N,128]
    float* gender = out + (size_t)N * 128;   // [N,2]
    float* label  = gender + (size_t)N * 2;  // [N,1]
    float* mu     = label + N;               // [N,64]
    float* lv     = mu + (size_t)N * 64;     // [N,64]
    float* z      = lv + (size_t)N * 64;     // [N,64]

    float *p_acc, *p_az, *p_wpack, *p_bpack, *p_muls;
    __half *p_tb, *p_hb;
    cudaGetSymbolAddress((void**)&p_tb, g_tb);
    cudaGetSymbolAddress((void**)&p_hb, g_hb);
    cudaGetSymbolAddress((void**)&p_acc, g_acc);
    cudaGetSymbolAddress((void**)&p_az, g_az);
    cudaGetSymbolAddress((void**)&p_wpack, g_wpack);
    cudaGetSymbolAddress((void**)&p_bpack, g_bpack);
    cudaGetSymbolAddress((void**)&p_muls, g_muls);

    const int T = 256;
    int nodeWarpBlocks = (int)(((size_t)N * 32 + T - 1) / T);
    int nScanBlocks = (N + 1023) / 1024;

    // 1) CSR build (parallel scan)
    cnt_zero<<<(N + T - 1) / T, T>>>(N);
    cnt_count<<<(E + T - 1) / T, T>>>(dst, E);
    dinv_fin<<<(N + T - 1) / T, T>>>(N);
    scan_blocks<<<nScanBlocks, 1024>>>(N);
    scan_bsum<<<1, 64>>>(nScanBlocks);
    add_bsum<<<(N + T - 1) / T, T>>>(N);
    csr_fill<<<(E + T - 1) / T, T>>>(src, dst, E);

    // 2) t = x @ W1 (fp16 table out; bias folded into agg epilogue)
    dim3 gg(1, (N + 127) / 128);
    sgemm128<<<gg, 256>>>(x, W1, nullptr, nullptr, p_tb, N, 128);

    // 3) h = relu(A_norm @ t + b1)  (fp16 gather -> fp16 table)
    agg128h<<<nodeWarpBlocks, T>>>(p_tb, p_hb, nullptr, b1, 1, N);

    // 4) ah = A_norm @ h  (fp16 gather -> fp32)
    agg128h<<<nodeWarpBlocks, T>>>(p_hb, nullptr, p_acc, nullptr, 0, N);

    // 5) [mu | logvar] = ah @ [Wmu|Wls] + [bmu|bls]
    pack_w<<<(128 * 64 + T - 1) / T, T>>>(Wmu, Wls, bmu, bls);
    sgemm128<<<gg, 256>>>(p_acc, p_wpack, p_bpack, p_muls, nullptr, N, 128);

    // 6) z = eps*exp(0.5*logvar)+mu; copy mu/lv to out
    size_t n64 = (size_t)N * 64;
    make_z<<<(int)((n64 + T - 1) / T), T>>>(eps, mu, lv, z, N);

    // 7) az = A_norm @ z  (fp32, keeps gender-logit path exact)
    agg64<<<nodeWarpBlocks, T>>>(z, p_az, N);

    // 8) recon_x = az @ Wdx + bdx
    sgemm128<<<gg, 256>>>(p_az, Wdx, bdx, recon, nullptr, N, 64);

    // 9) gender (gumbel) + logits_label
    heads<<<nodeWarpBlocks, T>>>(z, u, Wg, bg, Wlc, blc, gender, label, N);
}

// round 4
// speedup vs baseline: 2.6934x; 1.2582x over previous
#include <cuda_runtime.h>
#include <cuda_fp16.h>
#include <math.h>

#define NMAX 50048
#define EMAX 1700000
#define NBLK ((NMAX + 1023) / 1024)

// ---------------- scratch (device globals) ----------------------------------
__device__ __half g_tb[(size_t)NMAX * 128];  // x@W1 (fp16 gather table)
__device__ __half g_hb[(size_t)NMAX * 128];  // hidden after relu (fp16 table)
__device__ float g_acc[(size_t)NMAX * 128];  // aggregated h (fp32)
__device__ float g_muls[(size_t)NMAX * 128]; // packed [mu | logvar]
__device__ float g_az[(size_t)NMAX * 64];    // aggregated z
__device__ float g_dinv[NMAX];               // deg^-0.5
__device__ int   g_cnt[NMAX];                // in-degree (real edges)
__device__ int   g_off[NMAX];                // CSR row offsets
__device__ int   g_cur[NMAX];                // fill cursors
__device__ int   g_bsum[NBLK];               // scan block sums
__device__ uint2 g_edge[EMAX];               // CSR (src, weight-bits)
__device__ __half g_w1h[128 * 128];          // W1 fp16
__device__ __half g_wdxh[64 * 128];          // Wdx fp16
__device__ __half g_wph[128 * 128];          // [Wmu|Wls] fp16 hi
__device__ __half g_wpl[128 * 128];          // [Wmu|Wls] fp16 lo (residual)
__device__ float g_bpack[128];               // [bmu | bls]

// ---------------- weight conversion -----------------------------------------
__global__ void cvt_weights(const float* __restrict__ W1, const float* __restrict__ Wdx,
                            const float* __restrict__ Wmu, const float* __restrict__ Wls,
                            const float* __restrict__ bmu, const float* __restrict__ bls)
{
    int i = blockIdx.x * blockDim.x + threadIdx.x;
    if (i < 128 * 128) g_w1h[i] = __float2half_rn(W1[i]);
    if (i < 64 * 128) g_wdxh[i] = __float2half_rn(Wdx[i]);
    if (i < 128 * 128) {
        int row = i >> 7, col = i & 127;
        float v = (col < 64) ? Wmu[row * 64 + col] : Wls[row * 64 + (col - 64)];
        __half h = __float2half_rn(v);
        g_wph[i] = h;
        g_wpl[i] = __float2half_rn(v - __half2float(h));
    }
    if (i < 64) { g_bpack[i] = bmu[i]; g_bpack[64 + i] = bls[i]; }
}

// ---------------- degree / CSR build ----------------------------------------
__global__ void cnt_zero(int n) {
    int i = blockIdx.x * blockDim.x + threadIdx.x;
    if (i < n) { g_cnt[i] = 0; g_cur[i] = 0; }
}
__global__ void cnt_count(const int* __restrict__ dst, int e) {
    int i = blockIdx.x * blockDim.x + threadIdx.x;
    if (i < e) atomicAdd(&g_cnt[dst[i]], 1);
}
__global__ void dinv_fin(int n) {
    int i = blockIdx.x * blockDim.x + threadIdx.x;
    if (i < n) g_dinv[i] = rsqrtf(1.0f + (float)g_cnt[i]);
}
__global__ __launch_bounds__(1024) void scan_blocks(int n) {
    __shared__ int sh[1024];
    int tid = threadIdx.x;
    int i = blockIdx.x * 1024 + tid;
    int v = (i < n) ? g_cnt[i] : 0;
    sh[tid] = v;
    __syncthreads();
#pragma unroll
    for (int off = 1; off < 1024; off <<= 1) {
        int t = (tid >= off) ? sh[tid - off] : 0;
        __syncthreads();
        sh[tid] += t;
        __syncthreads();
    }
    if (i < n) g_off[i] = sh[tid] - v;
    if (tid == 1023) g_bsum[blockIdx.x] = sh[1023];
}
__global__ __launch_bounds__(64) void scan_bsum(int nb) {
    __shared__ int sh[64];
    int tid = threadIdx.x;
    int v = (tid < nb) ? g_bsum[tid] : 0;
    sh[tid] = v;
    __syncthreads();
#pragma unroll
    for (int off = 1; off < 64; off <<= 1) {
        int t = (tid >= off) ? sh[tid - off] : 0;
        __syncthreads();
        sh[tid] += t;
        __syncthreads();
    }
    if (tid < nb) g_bsum[tid] = sh[tid] - v;
}
__global__ void add_bsum(int n) {
    int i = blockIdx.x * blockDim.x + threadIdx.x;
    if (i < n) g_off[i] += g_bsum[i >> 10];
}
__global__ void csr_fill(const int* __restrict__ src, const int* __restrict__ dst, int e) {
    int i = blockIdx.x * blockDim.x + threadIdx.x;
    if (i >= e) return;
    int s = src[i], d = dst[i];
    int pos = g_off[d] + atomicAdd(&g_cur[d], 1);
    float w = g_dinv[s] * g_dinv[d];
    g_edge[pos] = make_uint2((unsigned)s, __float_as_uint(w));
}

// ---------------- fp16 gather helpers ----------------------------------------
__device__ __forceinline__ void acc_h4(float4& acc, uint2 q, float w) {
    __half2 p0 = *reinterpret_cast<__half2*>(&q.x);
    __half2 p1 = *reinterpret_cast<__half2*>(&q.y);
    float2 f0 = __half22float2(p0);
    float2 f1 = __half22float2(p1);
    acc.x += w * f0.x; acc.y += w * f0.y;
    acc.z += w * f1.x; acc.w += w * f1.y;
}

// ---------------- aggregation: warp per node, 128-wide, fp16 table -----------
__global__ __launch_bounds__(256) void agg128h(
    const __half* __restrict__ feat, __half* __restrict__ outh,
    float* __restrict__ outf, const float* __restrict__ bias, int doRelu, int n)
{
    int node = (blockIdx.x * blockDim.x + threadIdx.x) >> 5;
    if (node >= n) return;
    int lane = threadIdx.x & 31;
    const uint2* fb = reinterpret_cast<const uint2*>(feat);

    float di = g_dinv[node];
    float4 acc = make_float4(0.f, 0.f, 0.f, 0.f);
    acc_h4(acc, __ldg(fb + (size_t)node * 32 + lane), di * di);

    int j = g_off[node];
    int jend = j + g_cnt[node];
    for (; j + 4 <= jend; j += 4) {
        uint2 e0 = g_edge[j], e1 = g_edge[j + 1], e2 = g_edge[j + 2], e3 = g_edge[j + 3];
        uint2 q0 = __ldg(fb + (size_t)e0.x * 32 + lane);
        uint2 q1 = __ldg(fb + (size_t)e1.x * 32 + lane);
        uint2 q2 = __ldg(fb + (size_t)e2.x * 32 + lane);
        uint2 q3 = __ldg(fb + (size_t)e3.x * 32 + lane);
        acc_h4(acc, q0, __uint_as_float(e0.y));
        acc_h4(acc, q1, __uint_as_float(e1.y));
        acc_h4(acc, q2, __uint_as_float(e2.y));
        acc_h4(acc, q3, __uint_as_float(e3.y));
    }
    for (; j < jend; j++) {
        uint2 e = g_edge[j];
        acc_h4(acc, __ldg(fb + (size_t)e.x * 32 + lane), __uint_as_float(e.y));
    }
    if (bias) {
        float4 b = __ldg(reinterpret_cast<const float4*>(bias) + lane);
        acc.x += b.x; acc.y += b.y; acc.z += b.z; acc.w += b.w;
    }
    if (doRelu) {
        acc.x = fmaxf(acc.x, 0.f); acc.y = fmaxf(acc.y, 0.f);
        acc.z = fmaxf(acc.z, 0.f); acc.w = fmaxf(acc.w, 0.f);
    }
    if (outh) {
        __half2 h0 = __floats2half2_rn(acc.x, acc.y);
        __half2 h1 = __floats2half2_rn(acc.z, acc.w);
        uint2 q;
        q.x = *reinterpret_cast<unsigned*>(&h0);
        q.y = *reinterpret_cast<unsigned*>(&h1);
        *(reinterpret_cast<uint2*>(outh) + (size_t)node * 32 + lane) = q;
    }
    if (outf) {
        *(reinterpret_cast<float4*>(outf + (size_t)node * 128) + lane) = acc;
    }
}

// ---------------- aggregation: warp per node, 64-wide, fp32 ------------------
__global__ __launch_bounds__(256) void agg64(
    const float* __restrict__ feat, float* __restrict__ out, int n)
{
    int node = (blockIdx.x * blockDim.x + threadIdx.x) >> 5;
    if (node >= n) return;
    int lane = threadIdx.x & 31;
    float di = g_dinv[node];
    float w0 = di * di;
    float2 self = __ldg(reinterpret_cast<const float2*>(feat + (size_t)node * 64) + lane);
    float2 acc = make_float2(self.x * w0, self.y * w0);

    int j = g_off[node];
    int jend = j + g_cnt[node];
    for (; j + 4 <= jend; j += 4) {
        uint2 e0 = g_edge[j], e1 = g_edge[j + 1], e2 = g_edge[j + 2], e3 = g_edge[j + 3];
        float2 v0 = __ldg(reinterpret_cast<const float2*>(feat + (size_t)e0.x * 64) + lane);
        float2 v1 = __ldg(reinterpret_cast<const float2*>(feat + (size_t)e1.x * 64) + lane);
        float2 v2 = __ldg(reinterpret_cast<const float2*>(feat + (size_t)e2.x * 64) + lane);
        float2 v3 = __ldg(reinterpret_cast<const float2*>(feat + (size_t)e3.x * 64) + lane);
        float wa = __uint_as_float(e0.y), wb = __uint_as_float(e1.y);
        float wc = __uint_as_float(e2.y), wd = __uint_as_float(e3.y);
        acc.x += wa * v0.x; acc.y += wa * v0.y;
        acc.x += wb * v1.x; acc.y += wb * v1.y;
        acc.x += wc * v2.x; acc.y += wc * v2.y;
        acc.x += wd * v3.x; acc.y += wd * v3.y;
    }
    for (; j < jend; j++) {
        uint2 e = g_edge[j];
        float w = __uint_as_float(e.y);
        float2 v = __ldg(reinterpret_cast<const float2*>(feat + (size_t)e.x * 64) + lane);
        acc.x += w * v.x; acc.y += w * v.y;
    }
    *(reinterpret_cast<float2*>(out + (size_t)node * 64) + lane) = acc;
}

// ---------------- HMMA helpers ------------------------------------------------
__device__ __forceinline__ void ldsm4(unsigned& r0, unsigned& r1, unsigned& r2,
                                      unsigned& r3, unsigned addr) {
    asm volatile("ldmatrix.sync.aligned.m8n8.x4.shared.b16 {%0,%1,%2,%3}, [%4];"
                 : "=r"(r0), "=r"(r1), "=r"(r2), "=r"(r3) : "r"(addr));
}
__device__ __forceinline__ void ldsm4t(unsigned& r0, unsigned& r1, unsigned& r2,
                                       unsigned& r3, unsigned addr) {
    asm volatile("ldmatrix.sync.aligned.m8n8.x4.trans.shared.b16 {%0,%1,%2,%3}, [%4];"
                 : "=r"(r0), "=r"(r1), "=r"(r2), "=r"(r3) : "r"(addr));
}
__device__ __forceinline__ void mma16816(float* d, const unsigned* a, const unsigned* b) {
    asm volatile("mma.sync.aligned.m16n8k16.row.col.f32.f16.f16.f32 "
                 "{%0,%1,%2,%3}, {%4,%5,%6,%7}, {%8,%9}, {%0,%1,%2,%3};"
                 : "+f"(d[0]), "+f"(d[1]), "+f"(d[2]), "+f"(d[3])
                 : "r"(a[0]), "r"(a[1]), "r"(a[2]), "r"(a[3]), "r"(b[0]), "r"(b[1]));
}

// ---------------- HMMA GEMM: C[N,128] = A[N,K](fp32) @ B[K,128](fp16) --------
// SPLIT=true: A and B carried as hi+lo fp16 pairs; D = Ah*Bh + Ah*Bl + Al*Bh
// (near-fp32 accuracy). Block: 128 rows x 128 cols, 8 warps (4 M x 2 N),
// warp tile 32x64 (2x8 m16n8k16 atoms).
template <bool SPLIT>
__global__ __launch_bounds__(256) void hgemm128(
    const float* __restrict__ A, const __half* __restrict__ Bh,
    const __half* __restrict__ Bl, const float* __restrict__ bias,
    float* __restrict__ C, __half* __restrict__ Ch, int N, int K)
{
    __shared__ __half sAh[128][24];
    __shared__ __half sBh[16][136];
    __shared__ __half sAl[SPLIT ? 128 : 1][SPLIT ? 24 : 1];
    __shared__ __half sBl[SPLIT ? 16 : 1][SPLIT ? 136 : 1];

    int tid = threadIdx.x;
    int lane = tid & 31;
    int wid = tid >> 5;
    int wm = (wid & 3) * 32;
    int wn = (wid >> 2) * 64;
    int row0 = blockIdx.y * 128;

    float acc[2][8][4];
#pragma unroll
    for (int i = 0; i < 2; i++)
#pragma unroll
        for (int j = 0; j < 8; j++)
#pragma unroll
            for (int k = 0; k < 4; k++) acc[i][j][k] = 0.f;

    int ar = tid >> 1, ak = (tid & 1) * 8;   // A: row ar, 8 floats at ak
    int br = tid & 15, bc = (tid >> 4) * 8;  // B: row br, 8 halves at bc

    unsigned sa_base = (unsigned)__cvta_generic_to_shared(&sAh[0][0]);
    unsigned sb_base = (unsigned)__cvta_generic_to_shared(&sBh[0][0]);
    unsigned sal_base = SPLIT ? (unsigned)__cvta_generic_to_shared(&sAl[0][0]) : 0;
    unsigned sbl_base = SPLIT ? (unsigned)__cvta_generic_to_shared(&sBl[0][0]) : 0;

    const int KSTEPS = K >> 4;
    for (int ks = 0; ks < KSTEPS; ks++) {
        int k0 = ks << 4;
        // ---- global -> smem ----
        float va[8] = {0, 0, 0, 0, 0, 0, 0, 0};
        if (row0 + ar < N) {
            const float* ap = A + (size_t)(row0 + ar) * K + k0 + ak;
            float4 f0 = *reinterpret_cast<const float4*>(ap);
            float4 f1 = *reinterpret_cast<const float4*>(ap + 4);
            va[0] = f0.x; va[1] = f0.y; va[2] = f0.z; va[3] = f0.w;
            va[4] = f1.x; va[5] = f1.y; va[6] = f1.z; va[7] = f1.w;
        }
        __half hh[8];
#pragma unroll
        for (int i = 0; i < 8; i++) hh[i] = __float2half_rn(va[i]);
        *reinterpret_cast<uint4*>(&sAh[ar][ak]) = *reinterpret_cast<uint4*>(hh);
        if (SPLIT) {
            __half hl[8];
#pragma unroll
            for (int i = 0; i < 8; i++)
                hl[i] = __float2half_rn(va[i] - __half2float(hh[i]));
            *reinterpret_cast<uint4*>(&sAl[ar][ak]) = *reinterpret_cast<uint4*>(hl);
        }
        *reinterpret_cast<uint4*>(&sBh[br][bc]) =
            *reinterpret_cast<const uint4*>(Bh + (size_t)(k0 + br) * 128 + bc);
        if (SPLIT) {
            *reinterpret_cast<uint4*>(&sBl[br][bc]) =
                *reinterpret_cast<const uint4*>(Bl + (size_t)(k0 + br) * 128 + bc);
        }
        __syncthreads();

        // ---- fragments ----
        unsigned afh[2][4], afl[2][4];
        int fr = lane & 15;
        int fc = (lane >> 4) * 8;
#pragma unroll
        for (int am = 0; am < 2; am++) {
            unsigned off = (unsigned)(((wm + am * 16 + fr) * 24 + fc) << 1);
            ldsm4(afh[am][0], afh[am][1], afh[am][2], afh[am][3], sa_base + off);
            if (SPLIT)
                ldsm4(afl[am][0], afl[am][1], afl[am][2], afl[am][3], sal_base + off);
        }
        unsigned bfh[8][2], bfl[8][2];
#pragma unroll
        for (int bn = 0; bn < 4; bn++) {
            unsigned off = (unsigned)((fr * 136 + wn + bn * 16 + fc) << 1);
            ldsm4t(bfh[bn * 2][0], bfh[bn * 2][1], bfh[bn * 2 + 1][0], bfh[bn * 2 + 1][1],
                   sb_base + off);
            if (SPLIT)
                ldsm4t(bfl[bn * 2][0], bfl[bn * 2][1], bfl[bn * 2 + 1][0],
                       bfl[bn * 2 + 1][1], sbl_base + off);
        }

        // ---- MMAs ----
#pragma unroll
        for (int am = 0; am < 2; am++)
#pragma unroll
            for (int an = 0; an < 8; an++) {
                mma16816(acc[am][an], afh[am], bfh[an]);
                if (SPLIT) {
                    mma16816(acc[am][an], afh[am], bfl[an]);
                    mma16816(acc[am][an], afl[am], bfh[an]);
                }
            }
        __syncthreads();
    }

    // ---- epilogue ----
#pragma unroll
    for (int am = 0; am < 2; am++) {
        int rr = row0 + wm + am * 16 + (lane >> 2);
#pragma unroll
        for (int an = 0; an < 8; an++) {
            int cc = wn + an * 8 + (lane & 3) * 2;
            float bv0 = bias ? __ldg(bias + cc) : 0.f;
            float bv1 = bias ? __ldg(bias + cc + 1) : 0.f;
            if (rr < N) {
                float v0 = acc[am][an][0] + bv0, v1 = acc[am][an][1] + bv1;
                if (C) *reinterpret_cast<float2*>(C + (size_t)rr * 128 + cc) = make_float2(v0, v1);
                if (Ch) *reinterpret_cast<__half2*>(Ch + (size_t)rr * 128 + cc) = __floats2half2_rn(v0, v1);
            }
            if (rr + 8 < N) {
                float v2 = acc[am][an][2] + bv0, v3 = acc[am][an][3] + bv1;
                if (C) *reinterpret_cast<float2*>(C + (size_t)(rr + 8) * 128 + cc) = make_float2(v2, v3);
                if (Ch) *reinterpret_cast<__half2*>(Ch + (size_t)(rr + 8) * 128 + cc) = __floats2half2_rn(v2, v3);
            }
        }
    }
}

// ---------------- z = eps*exp(0.5*lv)+mu; copy mu/lv to out ------------------
__global__ void make_z(const float* __restrict__ eps,
                       float* __restrict__ mu_o, float* __restrict__ lv_o,
                       float* __restrict__ z_o, int n)
{
    size_t idx = (size_t)blockIdx.x * blockDim.x + threadIdx.x;
    if (idx >= (size_t)n * 64) return;
    size_t row = idx >> 6;
    int col = (int)(idx & 63);
    float mu = g_muls[row * 128 + col];
    float lv = g_muls[row * 128 + 64 + col];
    mu_o[idx] = mu;
    lv_o[idx] = lv;
    z_o[idx] = eps[idx] * expf(0.5f * lv) + mu;
}

// ---------------- heads: gender (gumbel) + logits_label ----------------------
__global__ __launch_bounds__(256) void heads(
    const float* __restrict__ z, const float* __restrict__ u,
    const float* __restrict__ Wg, const float* __restrict__ bg,
    const float* __restrict__ Wlc, const float* __restrict__ blc,
    float* __restrict__ gender, float* __restrict__ label, int n)
{
    int node = (blockIdx.x * blockDim.x + threadIdx.x) >> 5;
    if (node >= n) return;
    int lane = threadIdx.x & 31;
    float2 a  = *(reinterpret_cast<const float2*>(g_az + (size_t)node * 64) + lane);
    float2 zz = __ldg(reinterpret_cast<const float2*>(z + (size_t)node * 64) + lane);
    int k = lane * 2;
    float p0 = a.x * Wg[k * 2 + 0] + a.y * Wg[(k + 1) * 2 + 0];
    float p1 = a.x * Wg[k * 2 + 1] + a.y * Wg[(k + 1) * 2 + 1];
    float pl = zz.x * Wlc[k] + zz.y * Wlc[k + 1];
#pragma unroll
    for (int off = 16; off; off >>= 1) {
        p0 += __shfl_xor_sync(0xffffffffu, p0, off);
        p1 += __shfl_xor_sync(0xffffffffu, p1, off);
        pl += __shfl_xor_sync(0xffffffffu, pl, off);
    }
    if (lane == 0) {
        float l0 = p0 + bg[0], l1 = p1 + bg[1];
        float u0 = u[(size_t)node * 2], u1 = u[(size_t)node * 2 + 1];
        float gn0 = -logf(-logf(u0 + 1e-20f) + 1e-20f);
        float gn1 = -logf(-logf(u1 + 1e-20f) + 1e-20f);
        float a0 = l0 + gn0, a1 = l1 + gn1;
        float m = fmaxf(a0, a1);
        float e0 = expf(a0 - m), e1 = expf(a1 - m);
        float inv = 1.0f / (e0 + e1);
        float s0 = e0 * inv, s1 = e1 * inv;
        float h0 = (s0 >= s1) ? 1.0f : 0.0f;
        float h1 = 1.0f - h0;
        gender[(size_t)node * 2 + 0] = (h0 - s0) + s0;
        gender[(size_t)node * 2 + 1] = (h1 - s1) + s1;
        label[node] = pl + blc[0];
    }
}

// ---------------- launch -----------------------------------------------------
extern "C" void kernel_launch(void* const* d_in, const int* in_sizes, int n_in,
                              void* d_out, int out_size) {
    const float* x   = (const float*)d_in[0];
    const int*   ei  = (const int*)d_in[1];
    const float* eps = (const float*)d_in[2];
    const float* u   = (const float*)d_in[3];
    const float* W1  = (const float*)d_in[4];
    const float* b1  = (const float*)d_in[5];
    const float* Wmu = (const float*)d_in[6];
    const float* bmu = (const float*)d_in[7];
    const float* Wls = (const float*)d_in[8];
    const float* bls = (const float*)d_in[9];
    const float* Wdx = (const float*)d_in[10];
    const float* bdx = (const float*)d_in[11];
    const float* Wg  = (const float*)d_in[12];
    const float* bg  = (const float*)d_in[13];
    const float* Wlc = (const float*)d_in[14];
    const float* blc = (const float*)d_in[15];

    const int N = in_sizes[0] / 128;
    const int E = in_sizes[1] / 2;
    const int* src = ei;
    const int* dst = ei + E;

    float* out    = (float*)d_out;
    float* recon  = out;                     // [N,128]
    float* gender = out + (size_t)N * 128;   // [N,2]
    float* label  = gender + (size_t)N * 2;  // [N,1]
    float* mu     = label + N;               // [N,64]
    float* lv     = mu + (size_t)N * 64;     // [N,64]
    float* z      = lv + (size_t)N * 64;     // [N,64]

    float *p_acc, *p_az, *p_bpack, *p_muls;
    __half *p_tb, *p_hb, *p_w1h, *p_wdxh, *p_wph, *p_wpl;
    cudaGetSymbolAddress((void**)&p_tb, g_tb);
    cudaGetSymbolAddress((void**)&p_hb, g_hb);
    cudaGetSymbolAddress((void**)&p_acc, g_acc);
    cudaGetSymbolAddress((void**)&p_az, g_az);
    cudaGetSymbolAddress((void**)&p_bpack, g_bpack);
    cudaGetSymbolAddress((void**)&p_muls, g_muls);
    cudaGetSymbolAddress((void**)&p_w1h, g_w1h);
    cudaGetSymbolAddress((void**)&p_wdxh, g_wdxh);
    cudaGetSymbolAddress((void**)&p_wph, g_wph);
    cudaGetSymbolAddress((void**)&p_wpl, g_wpl);

    const int T = 256;
    int nodeWarpBlocks = (int)(((size_t)N * 32 + T - 1) / T);
    int nScanBlocks = (N + 1023) / 1024;

    // 0) weight conversion (independent of graph work)
    cvt_weights<<<(128 * 128 + T - 1) / T, T>>>(W1, Wdx, Wmu, Wls, bmu, bls);

    // 1) CSR build
    cnt_zero<<<(N + T - 1) / T, T>>>(N);
    cnt_count<<<(E + T - 1) / T, T>>>(dst, E);
    dinv_fin<<<(N + T - 1) / T, T>>>(N);
    scan_blocks<<<nScanBlocks, 1024>>>(N);
    scan_bsum<<<1, 64>>>(nScanBlocks);
    add_bsum<<<(N + T - 1) / T, T>>>(N);
    csr_fill<<<(E + T - 1) / T, T>>>(src, dst, E);

    // 2) t = x @ W1  (HMMA fp16, fp16 table out)
    dim3 gg(1, (N + 127) / 128);
    hgemm128<false><<<gg, 256>>>(x, p_w1h, nullptr, nullptr, nullptr, p_tb, N, 128);

    // 3) h = relu(A_norm @ t + b1)
    agg128h<<<nodeWarpBlocks, T>>>(p_tb, p_hb, nullptr, b1, 1, N);

    // 4) ah = A_norm @ h
    agg128h<<<nodeWarpBlocks, T>>>(p_hb, nullptr, p_acc, nullptr, 0, N);

    // 5) [mu | logvar] = ah @ [Wmu|Wls] + [bmu|bls]  (split-fp16 HMMA ~ fp32)
    hgemm128<true><<<gg, 256>>>(p_acc, p_wph, p_wpl, p_bpack, p_muls, nullptr, N, 128);

    // 6) z = eps*exp(0.5*logvar)+mu
    size_t n64 = (size_t)N * 64;
    make_z<<<(int)((n64 + T - 1) / T), T>>>(eps, mu, lv, z, N);

    // 7) az = A_norm @ z (fp32 — gender-logit path)
    agg64<<<nodeWarpBlocks, T>>>(z, p_az, N);

    // 8) recon_x = az @ Wdx + bdx  (HMMA fp16)
    hgemm128<false><<<gg, 256>>>(p_az, p_wdxh, nullptr, bdx, recon, nullptr, N, 64);

    // 9) gender (gumbel) + logits_label
    heads<<<nodeWarpBlocks, T>>>(z, u, Wg, bg, Wlc, blc, gender, label, N);
}